// round 4
// baseline (speedup 1.0000x reference)
#include <cuda_runtime.h>

// DepthToSpace, block_size=2
// in : x[16, 256, 128, 128] fp32
// out: y[16,  64, 256, 256] fp32
// out[b, dd, 2h+i, 2w+k] = x[b, i*128 + k*64 + dd, h, w]
//
// Per-thread: 8 consecutive output floats (ow = 8q..8q+7) of one output row,
// built from one float4 of channel c0 = i*128+dd and one float4 of c1 = c0+64
// (w = 4q..4q+3). Two LDG.128 + two STG.128 per thread, fully coalesced.

#define B_   16
#define C_   256
#define H_   128
#define W_   128
#define D_   64          // out channels
#define OH_  256
#define OW8_ 32          // out width / 8 (work items per output row)

// distance between channel c and c+64 in float4 units: 64 * H_ * (W_/4)
#define C64_STRIDE_F4 (64 * H_ * (W_ / 4))

__global__ __launch_bounds__(256) void d2s_kernel(
    const float4* __restrict__ x4, float4* __restrict__ out4)
{
    const int tid = blockIdx.x * blockDim.x + threadIdx.x;   // [0, 16*64*256*32)

    const int q   = tid & (OW8_ - 1);     // 8-float chunk within output row
    const int t1  = tid >> 5;
    const int oh  = t1 & (OH_ - 1);
    const int bd  = t1 >> 8;              // b*64 + dd
    const int dd  = bd & (D_ - 1);
    const int b   = bd >> 6;

    const int h = oh >> 1;
    const int i = oh & 1;
    const int c0 = i * 128 + dd;          // k=0 channel; k=1 channel is c0+64

    // float4 index of x[b, c0, h, 4q]
    const int base = (( (b * C_ + c0) * H_ + h ) * (W_ / 4)) + q;

    const float4 a0 = x4[base];                   // c0: w = 4q .. 4q+3
    const float4 a1 = x4[base + C64_STRIDE_F4];   // c1: w = 4q .. 4q+3

    // output float4 index: row (b,dd,oh) has 64 float4s; this thread owns 2q, 2q+1
    const int obase = t1 * 64 + 2 * q;
    out4[obase]     = make_float4(a0.x, a1.x, a0.y, a1.y);   // ow 8q .. 8q+3
    out4[obase + 1] = make_float4(a0.z, a1.z, a0.w, a1.w);   // ow 8q+4 .. 8q+7
}

extern "C" void kernel_launch(void* const* d_in, const int* in_sizes, int n_in,
                              void* d_out, int out_size)
{
    const float4* x4 = (const float4*)d_in[0];
    float4* out4 = (float4*)d_out;

    const unsigned total_threads = B_ * D_ * OH_ * OW8_;   // 8,388,608
    d2s_kernel<<<total_threads / 256u, 256>>>(x4, out4);
}